// round 1
// baseline (speedup 1.0000x reference)
#include <cuda_runtime.h>
#include <math.h>

#define T_STEPS 2048
#define BATCH   16
#define DDIM    1024
#define NPROJ   448           // 384 (kv) + 64 (q)
#define NOUT    (T_STEPS*BATCH*64)
#define MSIZE   (3*BATCH*64*64)

// Scratch for projections (no cudaMalloc allowed): 2048*16*448 floats = 58.7 MB
__device__ float g_proj[(size_t)T_STEPS * BATCH * NPROJ];

// ---------------------------------------------------------------------------
// Kernel 1: fused projection GEMM.
// C[r][p] = sum_d X[r][d] * W[p][d], r in [0,32768), p in [0,448)
// rows p<384 come from W_kv, rows >=384 from W_q. NT layout (both K-major).
// 64x64 block tile, 16-wide K tile, 256 threads, 4x4 micro-tile per thread.
// ---------------------------------------------------------------------------
__global__ __launch_bounds__(256) void gemm_proj(
    const float* __restrict__ X,
    const float* __restrict__ Wkv,
    const float* __restrict__ Wq)
{
    __shared__ __align__(16) float Xs[16][64];
    __shared__ __align__(16) float Ws[16][64];

    const int bn = blockIdx.x * 64;   // output col tile (0..6)
    const int bm = blockIdx.y * 64;   // output row tile (0..511)
    const int tid = threadIdx.x;
    const int tx = tid & 15;
    const int ty = tid >> 4;
    const int lr = tid >> 2;          // load row within tile (0..63)
    const int lc = (tid & 3) * 4;     // load k offset (0,4,8,12)

    float acc[4][4];
#pragma unroll
    for (int a = 0; a < 4; a++)
#pragma unroll
        for (int c = 0; c < 4; c++) acc[a][c] = 0.f;

    const float* xrow = X + (size_t)(bm + lr) * DDIM + lc;
    const int wr = bn + lr;
    const float* wrow = (wr < 384 ? Wkv + (size_t)wr * DDIM
                                  : Wq + (size_t)(wr - 384) * DDIM) + lc;

    for (int k0 = 0; k0 < DDIM; k0 += 16) {
        float4 xv = *(const float4*)(xrow + k0);
        float4 wv = *(const float4*)(wrow + k0);
        Xs[lc + 0][lr] = xv.x; Xs[lc + 1][lr] = xv.y;
        Xs[lc + 2][lr] = xv.z; Xs[lc + 3][lr] = xv.w;
        Ws[lc + 0][lr] = wv.x; Ws[lc + 1][lr] = wv.y;
        Ws[lc + 2][lr] = wv.z; Ws[lc + 3][lr] = wv.w;
        __syncthreads();
#pragma unroll
        for (int kk = 0; kk < 16; kk++) {
            float4 xr4 = *(const float4*)&Xs[kk][ty * 4];
            float4 wr4 = *(const float4*)&Ws[kk][tx * 4];
            float xa[4] = {xr4.x, xr4.y, xr4.z, xr4.w};
            float wb[4] = {wr4.x, wr4.y, wr4.z, wr4.w};
#pragma unroll
            for (int a = 0; a < 4; a++)
#pragma unroll
                for (int c = 0; c < 4; c++)
                    acc[a][c] = fmaf(xa[a], wb[c], acc[a][c]);
        }
        __syncthreads();
    }
#pragma unroll
    for (int a = 0; a < 4; a++) {
        float4 o = {acc[a][0], acc[a][1], acc[a][2], acc[a][3]};
        *(float4*)&g_proj[(size_t)(bm + ty * 4 + a) * NPROJ + bn + tx * 4] = o;
    }
}

// ---------------------------------------------------------------------------
// Kernel 2: recurrent scan. One CTA per batch b (16 CTAs), 384 threads.
// Thread (g, i, h): g = k-index (0..2), i = row (0..63), h = half (0/1).
// Owns Mr = M[g][i][32h..32h+32) and MTr = M[g]^T[i][32h..] = M[g][32h+j][i].
// Per step:
//   kn = k / (||k|| + eps)
//   thread's M[g] acts as gater for group gm1 = (g+2)%3  (gater[k] = M[k+1])
//   rg_pre[gm1][i] = M[g] row i . kn[gm1];  cg_pre[gm1][i] = MT[g] row i . kn[gm1]
//   retrieved[g][i] = M[g] row i . kn[g]
//   gates via sigmoid(+B_gates), delta = v - retrieved
//   M    <- rg[i]*M*cg[j] + delta[i]*kn[j]     (row form)
//   MT   <- rg[j]*MT*cg[i] + delta[j]*kn[i]    (transposed form)
//   out[t,b,:] = silu(M_new[0] @ q)
// ---------------------------------------------------------------------------
__device__ __forceinline__ float sigmoidf_(float x) {
    return 1.0f / (1.0f + expf(-x));
}

__global__ __launch_bounds__(384) void scan_kernel(
    const float* __restrict__ M_init,
    const float* __restrict__ B_gates,
    float* __restrict__ out,
    int write_M)
{
    const int b   = blockIdx.x;        // 0..15
    const int tid = threadIdx.x;       // 0..383
    const int g   = tid >> 7;          // 0..2
    const int r   = tid & 127;
    const int i   = r >> 1;            // 0..63
    const int h   = tid & 1;           // half
    const int gm1 = (g + 2) % 3;       // group this thread's M gates for

    __shared__ __align__(16) float raw[NPROJ];    // k|v per k (128 each) + q at 384
    __shared__ __align__(16) float kn[3][64];
    __shared__ __align__(16) float rgp[3][64];    // pre-activation, then gate
    __shared__ __align__(16) float cgp[3][64];
    __shared__ __align__(16) float dl[3][64];
    __shared__ float rns[3];

    float Mr[32], MTr[32];
    {
        const float* Mi = M_init + ((size_t)(g * BATCH + b)) * 4096;
#pragma unroll
        for (int j = 0; j < 32; j++) {
            Mr[j]  = Mi[i * 64 + 32 * h + j];
            MTr[j] = Mi[(32 * h + j) * 64 + i];
        }
    }
    const float bg = B_gates[g * 64 + i];

    for (int t = 0; t < T_STEPS; t++) {
        const float* prow = g_proj + ((size_t)t * BATCH + b) * NPROJ;
        // --- stage projection row into smem ---
        if (tid < NPROJ / 4)
            ((float4*)raw)[tid] = ((const float4*)prow)[tid];
        __syncthreads();

        // --- sum of squares per k (warps 0..2) ---
        const int wid = tid >> 5, lane = tid & 31;
        if (wid < 3) {
            float a0 = raw[wid * 128 + lane];
            float a1 = raw[wid * 128 + 32 + lane];
            float s = a0 * a0 + a1 * a1;
#pragma unroll
            for (int o = 16; o; o >>= 1)
                s += __shfl_xor_sync(0xffffffff, s, o);
            if (lane == 0) rns[wid] = 1.0f / (sqrtf(s) + 1e-6f);
        }
        __syncthreads();

        if (tid < 192) {
            const int gg = tid >> 6, ii = tid & 63;
            kn[gg][ii] = raw[gg * 128 + ii] * rns[gg];
        }
        __syncthreads();

        // --- three half-row dots ---
        float rpart = 0.f, apart = 0.f, cpart = 0.f;
        {
            const float4* kg  = (const float4*)(kn[g]   + 32 * h);
            const float4* kgm = (const float4*)(kn[gm1] + 32 * h);
#pragma unroll
            for (int j4 = 0; j4 < 8; j4++) {
                float4 a = kg[j4];
                float4 c = kgm[j4];
                rpart = fmaf(Mr[4*j4+0], a.x, rpart);
                rpart = fmaf(Mr[4*j4+1], a.y, rpart);
                rpart = fmaf(Mr[4*j4+2], a.z, rpart);
                rpart = fmaf(Mr[4*j4+3], a.w, rpart);
                apart = fmaf(Mr[4*j4+0], c.x, apart);
                apart = fmaf(Mr[4*j4+1], c.y, apart);
                apart = fmaf(Mr[4*j4+2], c.z, apart);
                apart = fmaf(Mr[4*j4+3], c.w, apart);
                cpart = fmaf(MTr[4*j4+0], c.x, cpart);
                cpart = fmaf(MTr[4*j4+1], c.y, cpart);
                cpart = fmaf(MTr[4*j4+2], c.z, cpart);
                cpart = fmaf(MTr[4*j4+3], c.w, cpart);
            }
        }
        rpart += __shfl_xor_sync(0xffffffff, rpart, 1);
        apart += __shfl_xor_sync(0xffffffff, apart, 1);
        cpart += __shfl_xor_sync(0xffffffff, cpart, 1);
        if (h == 0) { rgp[gm1][i] = apart; cgp[gm1][i] = cpart; }
        __syncthreads();

        // --- gates + delta (one thread per (g,i)) ---
        if (h == 0) {
            float rgv = sigmoidf_(rgp[g][i] + bg);
            float cgv = sigmoidf_(cgp[g][i] + bg);
            float dv  = raw[g * 128 + 64 + i] - rpart;
            rgp[g][i] = rgv; cgp[g][i] = cgv; dl[g][i] = dv;
        }
        __syncthreads();

        const float rg_i = rgp[g][i];
        const float cg_i = cgp[g][i];
        const float d_i  = dl[g][i];
        const float kn_i = kn[g][i];

        // --- rank-1 + gated update of M and MT half-rows ---
        {
            const float4* cgv4 = (const float4*)(cgp[g] + 32 * h);
            const float4* knv4 = (const float4*)(kn[g]  + 32 * h);
            const float4* rgv4 = (const float4*)(rgp[g] + 32 * h);
            const float4* dv4  = (const float4*)(dl[g]  + 32 * h);
#pragma unroll
            for (int j4 = 0; j4 < 8; j4++) {
                float4 cg4 = cgv4[j4];
                float4 kn4 = knv4[j4];
                float4 rg4 = rgv4[j4];
                float4 d4  = dv4[j4];
                Mr[4*j4+0] = fmaf(rg_i * Mr[4*j4+0], cg4.x, d_i * kn4.x);
                Mr[4*j4+1] = fmaf(rg_i * Mr[4*j4+1], cg4.y, d_i * kn4.y);
                Mr[4*j4+2] = fmaf(rg_i * Mr[4*j4+2], cg4.z, d_i * kn4.z);
                Mr[4*j4+3] = fmaf(rg_i * Mr[4*j4+3], cg4.w, d_i * kn4.w);
                MTr[4*j4+0] = fmaf(rg4.x * MTr[4*j4+0], cg_i, d4.x * kn_i);
                MTr[4*j4+1] = fmaf(rg4.y * MTr[4*j4+1], cg_i, d4.y * kn_i);
                MTr[4*j4+2] = fmaf(rg4.z * MTr[4*j4+2], cg_i, d4.z * kn_i);
                MTr[4*j4+3] = fmaf(rg4.w * MTr[4*j4+3], cg_i, d4.w * kn_i);
            }
        }

        // --- output: silu(M_new[0] @ q) ---
        if (g == 0) {
            float s = 0.f;
            const float4* qv = (const float4*)(raw + 384 + 32 * h);
#pragma unroll
            for (int j4 = 0; j4 < 8; j4++) {
                float4 q4 = qv[j4];
                s = fmaf(Mr[4*j4+0], q4.x, s);
                s = fmaf(Mr[4*j4+1], q4.y, s);
                s = fmaf(Mr[4*j4+2], q4.z, s);
                s = fmaf(Mr[4*j4+3], q4.w, s);
            }
            s += __shfl_xor_sync(0xffffffff, s, 1);
            if (h == 0)
                out[((size_t)t * BATCH + b) * 64 + i] = s * sigmoidf_(s);
        }
        __syncthreads();  // protect raw/kn/gates from next iteration's writes
    }

    // --- M_final ---
    if (write_M) {
        float* Mo = out + NOUT + ((size_t)(g * BATCH + b)) * 4096
                    + (size_t)i * 64 + 32 * h;
#pragma unroll
        for (int j = 0; j < 32; j++) Mo[j] = Mr[j];
    }
}

// ---------------------------------------------------------------------------
extern "C" void kernel_launch(void* const* d_in, const int* in_sizes, int n_in,
                              void* d_out, int out_size)
{
    // Bind inputs by element count (all sizes distinct; robust to ordering).
    const float *x = nullptr, *Mi = nullptr, *Wkv = nullptr,
                *Wq = nullptr, *Bg = nullptr;
    for (int idx = 0; idx < n_in; idx++) {
        switch (in_sizes[idx]) {
            case 33554432: x   = (const float*)d_in[idx]; break; // x (2048,16,1024)
            case 196608:   Mi  = (const float*)d_in[idx]; break; // M_init (3,16,64,64)
            case 393216:   Wkv = (const float*)d_in[idx]; break; // W_kv (384,1024)
            case 65536:    Wq  = (const float*)d_in[idx]; break; // W_q (64,1024)
            case 192:      Bg  = (const float*)d_in[idx]; break; // B_gates (3,64)
        }
    }
    // Positional fallback if any size changed.
    if (!x || !Mi || !Wkv || !Wq || !Bg) {
        x   = (const float*)d_in[0];
        Mi  = (const float*)d_in[1];
        Wkv = (const float*)d_in[2];
        Wq  = (const float*)d_in[3];
        Bg  = (const float*)d_in[4];
    }

    gemm_proj<<<dim3(NPROJ / 64, (T_STEPS * BATCH) / 64), 256>>>(x, Wkv, Wq);

    const int write_M = (out_size >= NOUT + MSIZE) ? 1 : 0;
    scan_kernel<<<BATCH, 384>>>(Mi, Bg, (float*)d_out, write_M);
}

// round 2
// speedup vs baseline: 1.3176x; 1.3176x over previous
#include <cuda_runtime.h>
#include <math.h>

#define T_STEPS 2048
#define BATCH   16
#define DDIM    1024
#define NPROJ   448           // 384 (kv) + 64 (q)
#define NOUT    (T_STEPS*BATCH*64)
#define MSIZE   (3*BATCH*64*64)
#define NSCAN   16
#define NCTA    148
#define NGEMM   (NCTA-NSCAN)
#define NRB     512           // row blocks of 64 rows (= 4 timesteps each)
#define NTILES  (NRB*7)

// Scratch (no cudaMalloc allowed)
__device__ float g_proj[(size_t)T_STEPS * BATCH * NPROJ];
__device__ int   g_cnt[NRB];

typedef unsigned long long ull;

__device__ __forceinline__ ull pk2(float lo, float hi) {
    ull r; asm("mov.b64 %0,{%1,%2};" : "=l"(r) : "f"(lo), "f"(hi)); return r;
}
__device__ __forceinline__ void upk2(ull v, float& a, float& b) {
    asm("mov.b64 {%0,%1},%2;" : "=f"(a), "=f"(b) : "l"(v));
}
__device__ __forceinline__ ull f2fma(ull a, ull b, ull c) {
    ull d; asm("fma.rn.f32x2 %0,%1,%2,%3;" : "=l"(d) : "l"(a), "l"(b), "l"(c)); return d;
}
__device__ __forceinline__ ull f2mul(ull a, ull b) {
    ull d; asm("mul.rn.f32x2 %0,%1,%2;" : "=l"(d) : "l"(a), "l"(b)); return d;
}
__device__ __forceinline__ int ldacq(const int* p) {
    int v; asm volatile("ld.acquire.gpu.global.b32 %0,[%1];" : "=r"(v) : "l"(p) : "memory"); return v;
}
__device__ __forceinline__ void redrel(int* p) {
    asm volatile("red.release.gpu.global.add.s32 [%0],1;" :: "l"(p) : "memory");
}
__device__ __forceinline__ float sigm(float x) { return 1.0f / (1.0f + expf(-x)); }

__global__ void zero_cnt() { if (threadIdx.x < NRB) g_cnt[threadIdx.x] = 0; }

struct GemmS { float Xs[16][64]; float Ws[16][64]; };
struct ScanS {
    float raw[2][NPROJ];     // double-buffered projection row
    float kn[3][64];
    float rgp[3][64];
    float cgp[3][64];
    float dl[3][64];
    float rns[3];
};

// ---------------------------------------------------------------------------
// Fused persistent kernel: CTAs [0,16) = scan consumers, [16,148) = GEMM
// producers. Producers write g_proj in t-major tile order and release
// per-rowblock counters; consumers acquire them.
// ---------------------------------------------------------------------------
__global__ __launch_bounds__(384, 1) void fused(
    const float* __restrict__ X,
    const float* __restrict__ Wkv,
    const float* __restrict__ Wq,
    const float* __restrict__ Mi,
    const float* __restrict__ Bg,
    float* __restrict__ out,
    int write_M)
{
    __shared__ __align__(16) union { GemmS g; ScanS s; } sm;
    const int tid = threadIdx.x;

    if (blockIdx.x >= NSCAN) {
        // ================= GEMM producer =================
        // 64x64 tile, 16-wide k, 256 active threads (128 idle but barrier-joined)
        const int tx = tid & 15;
        const int ty = tid >> 4;          // valid micro-tile coords for tid<256
        const int lr = tid >> 2;
        const int lc = (tid & 3) * 4;

        for (int tt = (int)blockIdx.x - NSCAN; tt < NTILES; tt += NGEMM) {
            const int rb = tt / 7, cb = tt % 7;
            const int bm = rb * 64, bn = cb * 64;

            float acc[4][4];
#pragma unroll
            for (int a = 0; a < 4; a++)
#pragma unroll
                for (int c = 0; c < 4; c++) acc[a][c] = 0.f;

            const float* xrow = X + (size_t)(bm + lr) * DDIM + lc;
            const int wr = bn + lr;
            const float* wrow = (wr < 384 ? Wkv + (size_t)wr * DDIM
                                          : Wq + (size_t)(wr - 384) * DDIM) + lc;

            for (int k0 = 0; k0 < DDIM; k0 += 16) {
                if (tid < 256) {
                    float4 xv = *(const float4*)(xrow + k0);
                    float4 wv = *(const float4*)(wrow + k0);
                    sm.g.Xs[lc + 0][lr] = xv.x; sm.g.Xs[lc + 1][lr] = xv.y;
                    sm.g.Xs[lc + 2][lr] = xv.z; sm.g.Xs[lc + 3][lr] = xv.w;
                    sm.g.Ws[lc + 0][lr] = wv.x; sm.g.Ws[lc + 1][lr] = wv.y;
                    sm.g.Ws[lc + 2][lr] = wv.z; sm.g.Ws[lc + 3][lr] = wv.w;
                }
                __syncthreads();
                if (tid < 256) {
#pragma unroll
                    for (int kk = 0; kk < 16; kk++) {
                        float4 xr4 = *(const float4*)&sm.g.Xs[kk][ty * 4];
                        float4 wr4 = *(const float4*)&sm.g.Ws[kk][tx * 4];
                        float xa[4] = {xr4.x, xr4.y, xr4.z, xr4.w};
                        float wb[4] = {wr4.x, wr4.y, wr4.z, wr4.w};
#pragma unroll
                        for (int a = 0; a < 4; a++)
#pragma unroll
                            for (int c = 0; c < 4; c++)
                                acc[a][c] = fmaf(xa[a], wb[c], acc[a][c]);
                    }
                }
                __syncthreads();
            }
            if (tid < 256) {
#pragma unroll
                for (int a = 0; a < 4; a++) {
                    float4 o = {acc[a][0], acc[a][1], acc[a][2], acc[a][3]};
                    *(float4*)&g_proj[(size_t)(bm + ty * 4 + a) * NPROJ + bn + tx * 4] = o;
                }
            }
            __syncthreads();                 // all tile stores happen-before signal
            if (tid == 0) redrel(&g_cnt[rb]);
        }
        return;
    }

    // ================= Scan consumer =================
    const int b   = blockIdx.x;
    const int g   = tid >> 7;           // 0..2
    const int i   = (tid & 127) >> 1;   // row 0..63
    const int h   = tid & 1;            // half
    const int gm1 = (g + 2) % 3;
    ScanS& S = sm.s;

    // M and M^T half-rows as packed f32x2 pairs
    ull Mr2[16], MTr2[16];
    {
        const float* M0 = Mi + ((size_t)(g * BATCH + b)) * 4096;
#pragma unroll
        for (int j = 0; j < 16; j++) {
            float2 a = *(const float2*)&M0[i * 64 + 32 * h + 2 * j];
            Mr2[j]  = pk2(a.x, a.y);
            MTr2[j] = pk2(M0[(32 * h + 2 * j) * 64 + i],
                          M0[(32 * h + 2 * j + 1) * 64 + i]);
        }
    }
    const float bg = Bg[g * 64 + i];

    // prologue: wait for rowblock 0, stage row (t=0, b)
    if (tid < 112) {
        while (ldacq(&g_cnt[0]) < 7) __nanosleep(64);
        ((float4*)S.raw[0])[tid] = ((const float4*)(g_proj + (size_t)b * NPROJ))[tid];
    }
    __syncthreads();

    const int wid = tid >> 5, lane = tid & 31;

    for (int t = 0; t < T_STEPS; t++) {
        const int cur = t & 1, nxt = cur ^ 1;

        // --- prefetch row t+1 into the other buffer (threads 192..303) ---
        if (tid >= 192 && tid < 304 && t + 1 < T_STEPS) {
            const int idx = tid - 192;
            const int r1 = (t + 1) * BATCH + b;
            const int rb1 = r1 >> 6;
            while (ldacq(&g_cnt[rb1]) < 7) __nanosleep(64);
            ((float4*)S.raw[nxt])[idx] =
                ((const float4*)(g_proj + (size_t)r1 * NPROJ))[idx];
        }

        // --- 1/(||k||+eps) per group (warps 0..2) ---
        if (wid < 3) {
            float a0 = S.raw[cur][wid * 128 + lane];
            float a1 = S.raw[cur][wid * 128 + 32 + lane];
            float ssq = a0 * a0 + a1 * a1;
#pragma unroll
            for (int o = 16; o; o >>= 1) ssq += __shfl_xor_sync(0xffffffffu, ssq, o);
            if (!lane) S.rns[wid] = 1.0f / (sqrtf(ssq) + 1e-6f);
        }
        __syncthreads();

        if (tid < 192)
            S.kn[tid >> 6][tid & 63] =
                S.raw[cur][(tid >> 6) * 128 + (tid & 63)] * S.rns[tid >> 6];
        __syncthreads();

        // --- packed half-row dots: retrieved, rg_pre(gm1), cg_pre(gm1) ---
        ull rp = 0ull, ap = 0ull, cp = 0ull;
        const ull* kg2 = (const ull*)(S.kn[g]   + 32 * h);
        const ull* km2 = (const ull*)(S.kn[gm1] + 32 * h);
#pragma unroll
        for (int j = 0; j < 16; j++) {
            ull kv = kg2[j], kmv = km2[j];
            rp = f2fma(Mr2[j],  kv,  rp);
            ap = f2fma(Mr2[j],  kmv, ap);
            cp = f2fma(MTr2[j], kmv, cp);
        }
        float rlo, rhi, alo, ahi, clo, chi;
        upk2(rp, rlo, rhi); upk2(ap, alo, ahi); upk2(cp, clo, chi);
        float rpart = rlo + rhi, apart = alo + ahi, cpart = clo + chi;
        rpart += __shfl_xor_sync(0xffffffffu, rpart, 1);
        apart += __shfl_xor_sync(0xffffffffu, apart, 1);
        cpart += __shfl_xor_sync(0xffffffffu, cpart, 1);
        if (!h) { S.rgp[gm1][i] = apart; S.cgp[gm1][i] = cpart; }
        __syncthreads();

        // --- gates + delta ---
        if (!h) {
            S.rgp[g][i] = sigm(S.rgp[g][i] + bg);
            S.cgp[g][i] = sigm(S.cgp[g][i] + bg);
            S.dl[g][i]  = S.raw[cur][g * 128 + 64 + i] - rpart;
        }
        __syncthreads();

        const float rg_i = S.rgp[g][i], cg_i = S.cgp[g][i];
        const float d_i  = S.dl[g][i],  kn_i = S.kn[g][i];
        const ull rgd = pk2(rg_i, rg_i), cgd = pk2(cg_i, cg_i);
        const ull dd  = pk2(d_i,  d_i),  knd = pk2(kn_i, kn_i);
        const ull* cg2 = (const ull*)(S.cgp[g] + 32 * h);
        const ull* kn2 = (const ull*)(S.kn[g]  + 32 * h);
        const ull* rg2 = (const ull*)(S.rgp[g] + 32 * h);
        const ull* dl2 = (const ull*)(S.dl[g]  + 32 * h);
#pragma unroll
        for (int j = 0; j < 16; j++) {
            ull c = cg2[j], k = kn2[j], r = rg2[j], d = dl2[j];
            Mr2[j]  = f2fma(f2mul(Mr2[j],  c), rgd, f2mul(k, dd));
            MTr2[j] = f2fma(f2mul(MTr2[j], r), cgd, f2mul(d, knd));
        }

        // --- output: silu(M_new[0] @ q) ---
        if (!g) {
            ull sq = 0ull;
            const ull* q2 = (const ull*)(S.raw[cur] + 384 + 32 * h);
#pragma unroll
            for (int j = 0; j < 16; j++) sq = f2fma(Mr2[j], q2[j], sq);
            float slo, shi; upk2(sq, slo, shi);
            float s = slo + shi;
            s += __shfl_xor_sync(0xffffffffu, s, 1);
            if (!h) out[((size_t)t * BATCH + b) * 64 + i] = s * sigm(s);
        }
        __syncthreads();   // protect smem for next iteration
    }

    if (write_M) {
        float* Mo = out + NOUT + ((size_t)(g * BATCH + b)) * 4096
                    + (size_t)i * 64 + 32 * h;
#pragma unroll
        for (int j = 0; j < 16; j++) {
            float a, c; upk2(Mr2[j], a, c);
            Mo[2 * j] = a; Mo[2 * j + 1] = c;
        }
    }
}

// ---------------------------------------------------------------------------
extern "C" void kernel_launch(void* const* d_in, const int* in_sizes, int n_in,
                              void* d_out, int out_size)
{
    const float *x = nullptr, *Mi = nullptr, *Wkv = nullptr,
                *Wq = nullptr, *Bg = nullptr;
    for (int idx = 0; idx < n_in; idx++) {
        switch (in_sizes[idx]) {
            case 33554432: x   = (const float*)d_in[idx]; break;
            case 196608:   Mi  = (const float*)d_in[idx]; break;
            case 393216:   Wkv = (const float*)d_in[idx]; break;
            case 65536:    Wq  = (const float*)d_in[idx]; break;
            case 192:      Bg  = (const float*)d_in[idx]; break;
        }
    }
    if (!x || !Mi || !Wkv || !Wq || !Bg) {
        x   = (const float*)d_in[0];
        Mi  = (const float*)d_in[1];
        Wkv = (const float*)d_in[2];
        Wq  = (const float*)d_in[3];
        Bg  = (const float*)d_in[4];
    }

    const int write_M = (out_size >= NOUT + MSIZE) ? 1 : 0;

    zero_cnt<<<1, 512>>>();
    fused<<<NCTA, 384>>>(x, Wkv, Wq, Mi, Bg, (float*)d_out, write_M);
}

// round 3
// speedup vs baseline: 1.6872x; 1.2805x over previous
#include <cuda_runtime.h>
#include <math.h>

#define T_STEPS 2048
#define BATCH   16
#define DDIM    1024
#define NPROJ   448           // 384 (kv) + 64 (q)
#define NOUT    (T_STEPS*BATCH*64)
#define MSIZE   (3*BATCH*64*64)
#define NSCAN   16
#define NCTA    148
#define NGEMM   (NCTA-NSCAN)
#define NRB     512           // row blocks of 64 rows (= 4 timesteps each)
#define NTILES  (NRB*7)

__device__ float g_proj[(size_t)T_STEPS * BATCH * NPROJ];
__device__ int   g_cnt[NRB];

typedef unsigned long long ull;

__device__ __forceinline__ ull pk2(float lo, float hi) {
    ull r; asm("mov.b64 %0,{%1,%2};" : "=l"(r) : "f"(lo), "f"(hi)); return r;
}
__device__ __forceinline__ void upk2(ull v, float& a, float& b) {
    asm("mov.b64 {%0,%1},%2;" : "=f"(a), "=f"(b) : "l"(v));
}
__device__ __forceinline__ ull f2fma(ull a, ull b, ull c) {
    ull d; asm("fma.rn.f32x2 %0,%1,%2,%3;" : "=l"(d) : "l"(a), "l"(b), "l"(c)); return d;
}
__device__ __forceinline__ ull f2mul(ull a, ull b) {
    ull d; asm("mul.rn.f32x2 %0,%1,%2;" : "=l"(d) : "l"(a), "l"(b)); return d;
}
__device__ __forceinline__ int ldacq(const int* p) {
    int v; asm volatile("ld.acquire.gpu.global.b32 %0,[%1];" : "=r"(v) : "l"(p) : "memory"); return v;
}
__device__ __forceinline__ void redrel(int* p) {
    asm volatile("red.release.gpu.global.add.s32 [%0],1;" :: "l"(p) : "memory");
}
__device__ __forceinline__ unsigned smem_u32(const void* p) {
    unsigned a;
    asm("{.reg .u64 t; cvta.to.shared.u64 t,%1; cvt.u32.u64 %0,t;}" : "=r"(a) : "l"(p));
    return a;
}
__device__ __forceinline__ void cp16(unsigned dst, const void* src) {
    asm volatile("cp.async.cg.shared.global [%0],[%1],16;" :: "r"(dst), "l"(src) : "memory");
}
__device__ __forceinline__ void cp_commit() {
    asm volatile("cp.async.commit_group;" ::: "memory");
}
__device__ __forceinline__ void cp_wait1() {
    asm volatile("cp.async.wait_group 1;" ::: "memory");
}
__device__ __forceinline__ float sigm(float x) {        // fast sigmoid
    return __fdividef(1.0f, 1.0f + __expf(-x));
}

__global__ void zero_cnt() { if (threadIdx.x < NRB) g_cnt[threadIdx.x] = 0; }

struct GemmS { float Xs[16][64]; float Ws[16][64]; };
struct ScanS {
    float raw[4][NPROJ];       // 4-deep ring, cp.async distance-2 prefetch
    float kn[2][3][64];        // normalized k, double-buffered
    float cgkn[2][3][128];     // interleaved {cg[2p],cg[2p+1],kn[2p],kn[2p+1]}
    float rgdl[2][3][128];     // interleaved {rg[2p],rg[2p+1],dl[2p],dl[2p+1]}
};

// ---------------------------------------------------------------------------
// Persistent fused kernel: CTAs [0,16) scan, [16,148) GEMM producers.
// ---------------------------------------------------------------------------
__global__ __launch_bounds__(384, 1) void fused(
    const float* __restrict__ X,
    const float* __restrict__ Wkv,
    const float* __restrict__ Wq,
    const float* __restrict__ Mi,
    const float* __restrict__ Bg,
    float* __restrict__ out,
    int write_M)
{
    __shared__ __align__(16) union { GemmS g; ScanS s; } sm;
    const int tid = threadIdx.x;

    if (blockIdx.x >= NSCAN) {
        // ================= GEMM producer =================
        const int tx = tid & 15;
        const int ty = tid >> 4;
        const int lr = tid >> 2;
        const int lc = (tid & 3) * 4;

        for (int tt = (int)blockIdx.x - NSCAN; tt < NTILES; tt += NGEMM) {
            const int rb = tt / 7, cb = tt % 7;
            const int bm = rb * 64, bn = cb * 64;

            float acc[4][4];
#pragma unroll
            for (int a = 0; a < 4; a++)
#pragma unroll
                for (int c = 0; c < 4; c++) acc[a][c] = 0.f;

            const float* xrow = X + (size_t)(bm + lr) * DDIM + lc;
            const int wr = bn + lr;
            const float* wrow = (wr < 384 ? Wkv + (size_t)wr * DDIM
                                          : Wq + (size_t)(wr - 384) * DDIM) + lc;

            for (int k0 = 0; k0 < DDIM; k0 += 16) {
                if (tid < 256) {
                    float4 xv = *(const float4*)(xrow + k0);
                    float4 wv = *(const float4*)(wrow + k0);
                    sm.g.Xs[lc + 0][lr] = xv.x; sm.g.Xs[lc + 1][lr] = xv.y;
                    sm.g.Xs[lc + 2][lr] = xv.z; sm.g.Xs[lc + 3][lr] = xv.w;
                    sm.g.Ws[lc + 0][lr] = wv.x; sm.g.Ws[lc + 1][lr] = wv.y;
                    sm.g.Ws[lc + 2][lr] = wv.z; sm.g.Ws[lc + 3][lr] = wv.w;
                }
                __syncthreads();
                if (tid < 256) {
#pragma unroll
                    for (int kk = 0; kk < 16; kk++) {
                        float4 xr4 = *(const float4*)&sm.g.Xs[kk][ty * 4];
                        float4 wr4 = *(const float4*)&sm.g.Ws[kk][tx * 4];
                        float xa[4] = {xr4.x, xr4.y, xr4.z, xr4.w};
                        float wb[4] = {wr4.x, wr4.y, wr4.z, wr4.w};
#pragma unroll
                        for (int a = 0; a < 4; a++)
#pragma unroll
                            for (int c = 0; c < 4; c++)
                                acc[a][c] = fmaf(xa[a], wb[c], acc[a][c]);
                    }
                }
                __syncthreads();
            }
            if (tid < 256) {
#pragma unroll
                for (int a = 0; a < 4; a++) {
                    float4 o = {acc[a][0], acc[a][1], acc[a][2], acc[a][3]};
                    *(float4*)&g_proj[(size_t)(bm + ty * 4 + a) * NPROJ + bn + tx * 4] = o;
                }
            }
            __syncthreads();
            if (tid == 0) redrel(&g_cnt[rb]);
        }
        return;
    }

    // ================= Scan consumer =================
    const int b    = blockIdx.x;
    const int g    = tid >> 7;           // 0..2
    const int i    = (tid & 127) >> 1;   // row 0..63
    const int h    = tid & 1;            // half
    const int gm1  = (g + 2) % 3;        // gate group this thread's M serves
    const int wid  = tid >> 5, lane = tid & 31;
    ScanS& S = sm.s;

    ull Mr2[16], MTr2[16];
    {
        const float* M0 = Mi + ((size_t)(g * BATCH + b)) * 4096;
#pragma unroll
        for (int j = 0; j < 16; j++) {
            float2 a = *(const float2*)&M0[i * 64 + 32 * h + 2 * j];
            Mr2[j]  = pk2(a.x, a.y);
            MTr2[j] = pk2(M0[(32 * h + 2 * j) * 64 + i],
                          M0[(32 * h + 2 * j + 1) * 64 + i]);
        }
    }
    const float bgm = Bg[gm1 * 64 + i];

    const bool pf = (tid >= 96 && tid < 208);   // 112 prefetch threads
    const int  pidx = tid - 96;

    // prologue: stage rows 0 and 1 (invariant: one pending group = next row)
    if (pf) {
        while (ldacq(&g_cnt[0]) < 7) __nanosleep(64);
        unsigned d0 = smem_u32(&S.raw[0][pidx * 4]);
        unsigned d1 = smem_u32(&S.raw[1][pidx * 4]);
        cp16(d0, g_proj + (size_t)b * NPROJ + pidx * 4);          cp_commit();
        cp16(d1, g_proj + (size_t)(BATCH + b) * NPROJ + pidx * 4); cp_commit();
        cp_wait1();   // row 0 complete, row 1 pending
    }
    __syncthreads();

    int cur = 0;
    for (int t = 0; t < T_STEPS; t++) {
        const int pb = t & 1;

        // ---- region 1: norm+kn (warps 0-2)  ||  prefetch row t+2 ----
        if (wid < 3) {
            float a0 = S.raw[cur][wid * 128 + lane];
            float a1 = S.raw[cur][wid * 128 + 32 + lane];
            float ssq = a0 * a0 + a1 * a1;
#pragma unroll
            for (int o = 16; o; o >>= 1) ssq += __shfl_xor_sync(0xffffffffu, ssq, o);
            float inv = __fdividef(1.0f, sqrtf(ssq) + 1e-6f);
            float k0 = a0 * inv, k1 = a1 * inv;
            S.kn[pb][wid][lane]      = k0;
            S.kn[pb][wid][lane + 32] = k1;
            S.cgkn[pb][wid][4 * (lane >> 1) + 2 + (lane & 1)]        = k0;
            S.cgkn[pb][wid][4 * ((lane + 32) >> 1) + 2 + (lane & 1)] = k1;
        }
        if (pf) {
            const int t2 = t + 2;
            if (t2 < T_STEPS) {
                const int r2 = t2 * BATCH + b;
                while (ldacq(&g_cnt[r2 >> 6]) < 7) __nanosleep(64);
                cp16(smem_u32(&S.raw[t2 & 3][pidx * 4]),
                     g_proj + (size_t)r2 * NPROJ + pidx * 4);
            }
            cp_commit();
            cp_wait1();   // row t+1 complete, row t+2 pending
        }
        __syncthreads();   // barrier B

        // ---- region 2: dots + gates (sigmoid fused, split across h) ----
        ull rp = 0ull, ap = 0ull, cp = 0ull;
        {
            const ulonglong2* kg = (const ulonglong2*)(S.kn[pb][g]   + 32 * h);
            const ulonglong2* km = (const ulonglong2*)(S.kn[pb][gm1] + 32 * h);
#pragma unroll
            for (int j4 = 0; j4 < 8; j4++) {
                ulonglong2 kv  = kg[j4];
                ulonglong2 kmv = km[j4];
                rp = f2fma(Mr2[2 * j4],     kv.x,  rp);
                rp = f2fma(Mr2[2 * j4 + 1], kv.y,  rp);
                ap = f2fma(Mr2[2 * j4],     kmv.x, ap);
                ap = f2fma(Mr2[2 * j4 + 1], kmv.y, ap);
                cp = f2fma(MTr2[2 * j4],     kmv.x, cp);
                cp = f2fma(MTr2[2 * j4 + 1], kmv.y, cp);
            }
        }
        float rlo, rhi, alo, ahi, clo, chi;
        upk2(rp, rlo, rhi); upk2(ap, alo, ahi); upk2(cp, clo, chi);
        float rpart = rlo + rhi, apart = alo + ahi, cpart = clo + chi;
        rpart += __shfl_xor_sync(0xffffffffu, rpart, 1);
        apart += __shfl_xor_sync(0xffffffffu, apart, 1);
        cpart += __shfl_xor_sync(0xffffffffu, cpart, 1);
        const int pi = 4 * (i >> 1);
        if (!h) {
            S.rgdl[pb][gm1][pi + (i & 1)]     = sigm(apart + bgm);            // row gate
            S.rgdl[pb][g]  [pi + 2 + (i & 1)] = S.raw[cur][g * 128 + 64 + i] - rpart; // delta
        } else {
            S.cgkn[pb][gm1][pi + (i & 1)]     = sigm(cpart + bgm);            // col gate
        }
        __syncthreads();   // barrier C

        // ---- region 3: gated rank-1 update + output ----
        const float cg_i = S.cgkn[pb][g][pi + (i & 1)];
        const float kn_i = S.cgkn[pb][g][pi + 2 + (i & 1)];
        const float rg_i = S.rgdl[pb][g][pi + (i & 1)];
        const float d_i  = S.rgdl[pb][g][pi + 2 + (i & 1)];
        const ull rgd = pk2(rg_i, rg_i), cgd = pk2(cg_i, cg_i);
        const ull dd  = pk2(d_i,  d_i),  knd = pk2(kn_i, kn_i);
        {
            const ulonglong2* ck = (const ulonglong2*)(S.cgkn[pb][g] + 64 * h);
            const ulonglong2* rd = (const ulonglong2*)(S.rgdl[pb][g] + 64 * h);
#pragma unroll
            for (int j = 0; j < 16; j++) {
                ulonglong2 a  = ck[j];   // {cg pair, kn pair}
                ulonglong2 bq = rd[j];   // {rg pair, dl pair}
                Mr2[j]  = f2fma(f2mul(Mr2[j],  a.x),  rgd, f2mul(a.y,  dd));
                MTr2[j] = f2fma(f2mul(MTr2[j], bq.x), cgd, f2mul(bq.y, knd));
            }
        }
        if (!g) {
            ull sq = 0ull;
            const ulonglong2* q2 = (const ulonglong2*)(S.raw[cur] + 384 + 32 * h);
#pragma unroll
            for (int j4 = 0; j4 < 8; j4++) {
                ulonglong2 q = q2[j4];
                sq = f2fma(Mr2[2 * j4],     q.x, sq);
                sq = f2fma(Mr2[2 * j4 + 1], q.y, sq);
            }
            float slo, shi; upk2(sq, slo, shi);
            float s = slo + shi;
            s += __shfl_xor_sync(0xffffffffu, s, 1);
            if (!h) out[((size_t)t * BATCH + b) * 64 + i] = s * sigm(s);
        }
        cur = (cur == 3) ? 0 : cur + 1;
        // no end-of-loop barrier: kn/gates double-buffered, raw 4-deep ring
    }

    if (write_M) {
        float* Mo = out + NOUT + ((size_t)(g * BATCH + b)) * 4096
                    + (size_t)i * 64 + 32 * h;
#pragma unroll
        for (int j = 0; j < 16; j++) {
            float a, c; upk2(Mr2[j], a, c);
            Mo[2 * j] = a; Mo[2 * j + 1] = c;
        }
    }
}

// ---------------------------------------------------------------------------
extern "C" void kernel_launch(void* const* d_in, const int* in_sizes, int n_in,
                              void* d_out, int out_size)
{
    const float *x = nullptr, *Mi = nullptr, *Wkv = nullptr,
                *Wq = nullptr, *Bg = nullptr;
    for (int idx = 0; idx < n_in; idx++) {
        switch (in_sizes[idx]) {
            case 33554432: x   = (const float*)d_in[idx]; break;
            case 196608:   Mi  = (const float*)d_in[idx]; break;
            case 393216:   Wkv = (const float*)d_in[idx]; break;
            case 65536:    Wq  = (const float*)d_in[idx]; break;
            case 192:      Bg  = (const float*)d_in[idx]; break;
        }
    }
    if (!x || !Mi || !Wkv || !Wq || !Bg) {
        x   = (const float*)d_in[0];
        Mi  = (const float*)d_in[1];
        Wkv = (const float*)d_in[2];
        Wq  = (const float*)d_in[3];
        Bg  = (const float*)d_in[4];
    }

    const int write_M = (out_size >= NOUT + MSIZE) ? 1 : 0;

    zero_cnt<<<1, 512>>>();
    fused<<<NCTA, 384>>>(x, Wkv, Wq, Mi, Bg, (float*)d_out, write_M);
}